// round 4
// baseline (speedup 1.0000x reference)
#include <cuda_runtime.h>
#include <math.h>

// Problem constants
#define B_  64
#define T_  512
#define H_  50
#define G_  200     // 4*H
#define F_  513
#define M_  (B_*T_) // 32768

// Scratch (device globals: allocation-free per harness rules)
__device__ float g_xg[(size_t)M_ * G_];   // 26.2 MB
__device__ float g_hs[(size_t)M_ * H_];   // 6.6 MB

typedef unsigned long long u64;

// ---------------- f32x2 packed helpers (sm_100+) ----------------
__device__ __forceinline__ u64 pk2(float lo, float hi) {
    u64 r;
    asm("mov.b64 %0, {%1, %2};" : "=l"(r) : "f"(lo), "f"(hi));
    return r;
}
__device__ __forceinline__ void upk2(u64 v, float& lo, float& hi) {
    asm("mov.b64 {%0, %1}, %2;" : "=f"(lo), "=f"(hi) : "l"(v));
}
__device__ __forceinline__ void fma2(u64& d, u64 a, u64 b) {
    asm("fma.rn.f32x2 %0, %1, %2, %0;" : "+l"(d) : "l"(a), "l"(b));
}
__device__ __forceinline__ void add2(u64& d, u64 a) {
    asm("add.rn.f32x2 %0, %0, %1;" : "+l"(d) : "l"(a));
}

// ============ C = A(MxK) * B(NxK)^T + bias(N) ============
// BM=256, BN=64, BK=8, TM=8, TN=8, 256 threads.
// B stored DUPLICATED in shared ({v,v}) so both operands of the f32x2 FMA
// come straight from LDS.128 — no per-iteration packing movs.
// Double-buffered shared + register prefetch: one sync per k-tile.
#define BM 256
#define BN 64
#define BK 8
#define SA_STRIDE (BM + 4)      // 260: 16B-aligned rows, conflict-free STS
#define SB_STRIDE (2*BN + 4)    // 132

__global__ void __launch_bounds__(256, 2)
gemm_abt_bias(const float* __restrict__ A, const float* __restrict__ Bm,
              const float* __restrict__ bias, float* __restrict__ C,
              int M, int N, int K)
{
    __shared__ __align__(16) float sA[2][BK][SA_STRIDE];
    __shared__ __align__(16) float sB[2][BK][SB_STRIDE];

    const int tid = threadIdx.x;
    const int tn  = tid & 7;     // 8 col groups (TN=8)
    const int tm  = tid >> 3;    // 32 row groups (TM=8)
    const int m0  = blockIdx.x * BM;
    const int n0  = blockIdx.y * BN;

    const int lk = tid & 7;      // k within tile for loads
    const int lr = tid >> 3;     // 0..31

    u64 acc[4][8];
#pragma unroll
    for (int i = 0; i < 4; i++)
#pragma unroll
        for (int j = 0; j < 8; j++) acc[i][j] = 0ULL;

    float ra[8];   // A prefetch: 256*8/256 = 8 per thread
    float rb[2];   // B prefetch: 64*8/256 = 2 per thread

    const int ktiles = (K + BK - 1) / BK;

    // --- prologue: tile 0 ---
    {
        int k = lk;
        bool kok = (k < K);
#pragma unroll
        for (int r = 0; r < 8; r++) {
            int m = m0 + lr + 32 * r;
            ra[r] = kok ? A[(size_t)m * K + k] : 0.f;
        }
#pragma unroll
        for (int r = 0; r < 2; r++) {
            int n = n0 + lr + 32 * r;
            rb[r] = (kok && n < N) ? Bm[(size_t)n * K + k] : 0.f;
        }
#pragma unroll
        for (int r = 0; r < 8; r++) sA[0][lk][lr + 32 * r] = ra[r];
#pragma unroll
        for (int r = 0; r < 2; r++)
            *(float2*)&sB[0][lk][2 * (lr + 32 * r)] = make_float2(rb[r], rb[r]);
    }
    __syncthreads();

    for (int kt = 0; kt < ktiles; kt++) {
        const int buf = kt & 1;

        // prefetch next tile into registers (LDG in flight during compute)
        if (kt + 1 < ktiles) {
            int k = (kt + 1) * BK + lk;
            bool kok = (k < K);
#pragma unroll
            for (int r = 0; r < 8; r++) {
                int m = m0 + lr + 32 * r;
                ra[r] = kok ? A[(size_t)m * K + k] : 0.f;
            }
#pragma unroll
            for (int r = 0; r < 2; r++) {
                int n = n0 + lr + 32 * r;
                rb[r] = (kok && n < N) ? Bm[(size_t)n * K + k] : 0.f;
            }
        }

        // compute
#pragma unroll
        for (int kk = 0; kk < BK; kk++) {
            const ulonglong2* pa = (const ulonglong2*)&sA[buf][kk][tm * 8];
            const ulonglong2* pb = (const ulonglong2*)&sB[buf][kk][tn * 16];
            ulonglong2 a01 = pa[0], a23 = pa[1];
            ulonglong2 b01 = pb[0], b23 = pb[1], b45 = pb[2], b67 = pb[3];
            u64 a[4] = { a01.x, a01.y, a23.x, a23.y };
            u64 b[8] = { b01.x, b01.y, b23.x, b23.y, b45.x, b45.y, b67.x, b67.y };
#pragma unroll
            for (int i = 0; i < 4; i++)
#pragma unroll
                for (int j = 0; j < 8; j++)
                    fma2(acc[i][j], a[i], b[j]);
        }

        // stage next tile into the other buffer
        if (kt + 1 < ktiles) {
            const int nb = buf ^ 1;
#pragma unroll
            for (int r = 0; r < 8; r++) sA[nb][lk][lr + 32 * r] = ra[r];
#pragma unroll
            for (int r = 0; r < 2; r++)
                *(float2*)&sB[nb][lk][2 * (lr + 32 * r)] = make_float2(rb[r], rb[r]);
        }
        __syncthreads();
    }

    // --- epilogue ---
    float bj[8];
#pragma unroll
    for (int j = 0; j < 8; j++) {
        int n = n0 + tn * 8 + j;
        bj[j] = (n < N) ? bias[n] : 0.f;
    }
    const bool vec = (n0 + BN <= N) && ((N & 3) == 0);

#pragma unroll
    for (int i = 0; i < 4; i++) {
        float lo[8], hi[8];
#pragma unroll
        for (int j = 0; j < 8; j++) {
            upk2(acc[i][j], lo[j], hi[j]);
            lo[j] += bj[j];
            hi[j] += bj[j];
        }
        size_t mlo = (size_t)(m0 + tm * 8 + 2 * i);
        float* C0 = C + mlo * N + n0 + tn * 8;
        float* C1 = C0 + N;
        if (vec) {
            ((float4*)C0)[0] = make_float4(lo[0], lo[1], lo[2], lo[3]);
            ((float4*)C0)[1] = make_float4(lo[4], lo[5], lo[6], lo[7]);
            ((float4*)C1)[0] = make_float4(hi[0], hi[1], hi[2], hi[3]);
            ((float4*)C1)[1] = make_float4(hi[4], hi[5], hi[6], hi[7]);
        } else {
#pragma unroll
            for (int j = 0; j < 8; j++) {
                int n = n0 + tn * 8 + j;
                if (n < N) { C0[j] = lo[j]; C1[j] = hi[j]; }
            }
        }
    }
}

// ============ LSTM recurrence over the BATCH axis ============
// T=512 independent lanes; 4 lanes per CTA (128 CTAs), 64 sequential steps.
// W_hh row lives in REGISTERS (50/thread). h is lane-interleaved float2 in
// shared so gate FMAs are f32x2 packed across lane pairs.
__device__ __forceinline__ float sigm_f(float x) {
    return 1.f / (1.f + __expf(-x));
}
__device__ __forceinline__ float tanh_f(float x) {
    return 2.f / (1.f + __expf(-2.f * x)) - 1.f;
}

__global__ void __launch_bounds__(256)
lstm_rec_kernel(const float* __restrict__ xg, const float* __restrict__ W_hh,
                const float* __restrict__ b_hh, float* __restrict__ hs)
{
    __shared__ __align__(8) float2 h01[H_], h23[H_];     // {lane0,lane1}, {lane2,lane3}
    __shared__ __align__(8) float2 g01[G_], g23[G_];

    const int tid   = threadIdx.x;
    const int lane0 = blockIdx.x * 4;

    float w[H_];
    float bh = 0.f;
    if (tid < G_) {
#pragma unroll
        for (int k = 0; k < H_; k++) w[k] = W_hh[tid * H_ + k];  // W_hh (200,50) row-major
        bh = b_hh[tid];
    }
    if (tid < H_) { h01[tid] = make_float2(0.f, 0.f); h23[tid] = make_float2(0.f, 0.f); }
    float c = 0.f;   // cell state (threads < 200)
    __syncthreads();

    for (int b = 0; b < B_; b++) {
        if (tid < G_) {
            const float* xr = xg + (size_t)(b * T_ + lane0) * G_ + tid;
            u64 a01  = pk2(xr[0]        + bh, xr[G_]     + bh);
            u64 a23  = pk2(xr[2 * G_]   + bh, xr[3 * G_] + bh);
            u64 a01b = 0ULL, a23b = 0ULL;
#pragma unroll
            for (int k = 0; k < H_; k += 2) {
                u64 hA0 = *(const u64*)&h01[k];
                u64 hA1 = *(const u64*)&h23[k];
                u64 hB0 = *(const u64*)&h01[k + 1];
                u64 hB1 = *(const u64*)&h23[k + 1];
                u64 wd0 = pk2(w[k],     w[k]);
                u64 wd1 = pk2(w[k + 1], w[k + 1]);
                fma2(a01,  hA0, wd0);
                fma2(a23,  hA1, wd0);
                fma2(a01b, hB0, wd1);
                fma2(a23b, hB1, wd1);
            }
            add2(a01, a01b);
            add2(a23, a23b);
            *(u64*)&g01[tid] = a01;
            *(u64*)&g23[tid] = a23;
        }
        __syncthreads();

        if (tid < 4 * H_) {           // 200 update threads: (lane l, unit hh)
            int l  = tid / H_;
            int hh = tid - l * H_;
            const float* gb = (l < 2) ? (const float*)g01 : (const float*)g23;
            int off = l & 1;
            float ig = gb[2 * hh            + off];
            float fg = gb[2 * (H_ + hh)     + off];
            float gg = gb[2 * (2 * H_ + hh) + off];
            float og = gb[2 * (3 * H_ + hh) + off];
            float si = sigm_f(ig);
            float sf = sigm_f(fg);
            float so = sigm_f(og);
            c = sf * c + si * tanh_f(gg);
            float h2 = so * tanh_f(c);
            float* hb = (l < 2) ? (float*)h01 : (float*)h23;
            hb[2 * hh + off] = h2;
            hs[(size_t)(b * T_ + lane0 + l) * H_ + hh] = h2;
        }
        __syncthreads();
    }
}

// ---------------- launch ----------------
extern "C" void kernel_launch(void* const* d_in, const int* in_sizes, int n_in,
                              void* d_out, int out_size)
{
    const float* x     = (const float*)d_in[0];   // (64,512,513)
    const float* W_ih  = (const float*)d_in[1];   // (200,513)
    const float* W_hh  = (const float*)d_in[2];   // (200,50)
    const float* b_ih  = (const float*)d_in[3];   // (200,)
    const float* b_hh  = (const float*)d_in[4];   // (200,)
    const float* W_out = (const float*)d_in[5];   // (513,50)
    const float* b_out = (const float*)d_in[6];   // (513,)
    float* out = (float*)d_out;                   // (64,512,513)

    float *xg, *hs;
    cudaGetSymbolAddress((void**)&xg, g_xg);
    cudaGetSymbolAddress((void**)&hs, g_hs);

    dim3 blk(256);

    // 1) xg = x @ W_ih^T + b_ih   (M=32768, N=200, K=513)
    gemm_abt_bias<<<dim3(M_ / BM, (G_ + BN - 1) / BN), blk>>>(x, W_ih, b_ih, xg, M_, G_, F_);

    // 2) batch-axis LSTM recurrence -> hs (32768, 50)
    lstm_rec_kernel<<<T_ / 4, blk>>>(xg, W_hh, b_hh, hs);

    // 3) out = hs @ W_out^T + b_out   (M=32768, N=513, K=50)
    gemm_abt_bias<<<dim3(M_ / BM, (F_ + BN - 1) / BN), blk>>>(hs, W_out, b_out, out, M_, F_, H_);
}

// round 5
// speedup vs baseline: 2.2597x; 2.2597x over previous
#include <cuda_runtime.h>
#include <math.h>

// Problem constants
#define B_   64
#define T_   512
#define H_   50
#define G_   200      // 4*H
#define F_   513
#define M_   (B_*T_)  // 32768
#define KP1  528      // F padded to multiple of 16 (16B-aligned rows)
#define KP3  64       // H padded to multiple of 16

// Scratch (device globals: allocation-free per harness rules)
__device__ float g_xpad[(size_t)M_ * KP1];    // 69.2 MB padded x
__device__ float g_wih [(size_t)G_ * KP1];    // padded W_ih (200 x 528)
__device__ float g_wout[(size_t)F_ * KP3];    // padded W_out (513 x 64)
__device__ float g_xg  [(size_t)M_ * G_];     // 26.2 MB gates
__device__ float g_hs  [(size_t)M_ * KP3];    // 8.4 MB hidden (padded rows)

typedef unsigned long long u64;

// ---------------- f32x2 packed helpers ----------------
__device__ __forceinline__ u64 pk2(float lo, float hi) {
    u64 r;
    asm("mov.b64 %0, {%1, %2};" : "=l"(r) : "f"(lo), "f"(hi));
    return r;
}
__device__ __forceinline__ void upk2(u64 v, float& lo, float& hi) {
    asm("mov.b64 {%0, %1}, %2;" : "=f"(lo), "=f"(hi) : "l"(v));
}
__device__ __forceinline__ void fma2(u64& d, u64 a, u64 b) {
    asm("fma.rn.f32x2 %0, %1, %2, %0;" : "+l"(d) : "l"(a), "l"(b));
}
__device__ __forceinline__ void add2(u64& d, u64 a) {
    asm("add.rn.f32x2 %0, %0, %1;" : "+l"(d) : "l"(a));
}

// ---------------- padding prepass ----------------
__global__ void pad_x_kernel(const float* __restrict__ x, float* __restrict__ xp)
{
    size_t i = (size_t)blockIdx.x * blockDim.x + threadIdx.x;   // over M_*KP1
    if (i >= (size_t)M_ * KP1) return;
    int m = (int)(i / KP1);
    int k = (int)(i - (size_t)m * KP1);
    xp[i] = (k < F_) ? x[(size_t)m * F_ + k] : 0.f;
}
__global__ void pad_w_kernel(const float* __restrict__ wih, const float* __restrict__ wout,
                             float* __restrict__ wihp, float* __restrict__ woutp)
{
    int i = blockIdx.x * blockDim.x + threadIdx.x;
    if (i < G_ * KP1) {
        int g = i / KP1, k = i - g * KP1;
        wihp[i] = (k < F_) ? wih[g * F_ + k] : 0.f;
    }
    if (i < F_ * KP3) {
        int f = i / KP3, k = i - f * KP3;
        woutp[i] = (k < H_) ? wout[f * H_ + k] : 0.f;
    }
}

// ============ C = A(M x KP) * B(N x KP)^T + bias(N) ============
// A, B have KP-padded 16B-aligned rows (zeros in pad). KP % 16 == 0.
// BM=128, BN=64, BK=16, TM=8, TN=4, 256 threads (16x16 map).
// acc = 16 u64 (32 regs) -> no spills at 2 CTAs/SM.
#define BM 128
#define BN 64
#define BK 16
#define SA_ST (BM + 4)   // 132 floats: 16B-aligned rows
#define SB_ST (BN + 4)   // 68

__global__ void __launch_bounds__(256, 2)
gemm_abt_bias(const float* __restrict__ A, const float* __restrict__ Bm,
              const float* __restrict__ bias, float* __restrict__ C,
              int M, int N, int KP)
{
    __shared__ __align__(16) float sA[2][BK][SA_ST];
    __shared__ __align__(16) float sB[2][BK][SB_ST];

    const int tid = threadIdx.x;
    const int tn  = tid & 15;          // 16 col groups x TN=4
    const int tm  = tid >> 4;          // 16 row groups x TM=8
    const int m0  = blockIdx.x * BM;
    const int n0  = blockIdx.y * BN;

    // load map (float4 granularity)
    const int lq  = tid & 3;           // k-quad 0..3 (k = 4*lq + j)
    const int lmA = tid >> 2;          // 0..63: A rows lmA, lmA+64
    const int lnB = tid >> 2;          // 0..63: B row

    u64 acc[4][4];
#pragma unroll
    for (int i = 0; i < 4; i++)
#pragma unroll
        for (int j = 0; j < 4; j++) acc[i][j] = 0ULL;

    float4 ra0, ra1, rb;
    const int ktiles = KP / BK;

    // --- prologue: fetch + stage tile 0 ---
    {
        const float* Ap = A + (size_t)(m0 + lmA) * KP + 4 * lq;
        ra0 = *(const float4*)Ap;
        ra1 = *(const float4*)(Ap + (size_t)64 * KP);
        int n = n0 + lnB;
        rb = (n < N) ? *(const float4*)(Bm + (size_t)n * KP + 4 * lq)
                     : make_float4(0.f, 0.f, 0.f, 0.f);
        sA[0][4 * lq + 0][lmA] = ra0.x; sA[0][4 * lq + 1][lmA] = ra0.y;
        sA[0][4 * lq + 2][lmA] = ra0.z; sA[0][4 * lq + 3][lmA] = ra0.w;
        sA[0][4 * lq + 0][lmA + 64] = ra1.x; sA[0][4 * lq + 1][lmA + 64] = ra1.y;
        sA[0][4 * lq + 2][lmA + 64] = ra1.z; sA[0][4 * lq + 3][lmA + 64] = ra1.w;
        sB[0][4 * lq + 0][lnB] = rb.x; sB[0][4 * lq + 1][lnB] = rb.y;
        sB[0][4 * lq + 2][lnB] = rb.z; sB[0][4 * lq + 3][lnB] = rb.w;
    }
    __syncthreads();

    for (int kt = 0; kt < ktiles; kt++) {
        const int buf = kt & 1;

        if (kt + 1 < ktiles) {
            const int k0 = (kt + 1) * BK;
            const float* Ap = A + (size_t)(m0 + lmA) * KP + k0 + 4 * lq;
            ra0 = *(const float4*)Ap;
            ra1 = *(const float4*)(Ap + (size_t)64 * KP);
            int n = n0 + lnB;
            rb = (n < N) ? *(const float4*)(Bm + (size_t)n * KP + k0 + 4 * lq)
                         : make_float4(0.f, 0.f, 0.f, 0.f);
        }

#pragma unroll
        for (int kk = 0; kk < BK; kk++) {
            const ulonglong2* pa = (const ulonglong2*)&sA[buf][kk][tm * 8];
            ulonglong2 a01 = pa[0], a23 = pa[1];
            float4 bf = *(const float4*)&sB[buf][kk][tn * 4];
            u64 a[4] = { a01.x, a01.y, a23.x, a23.y };
            u64 b[4] = { pk2(bf.x, bf.x), pk2(bf.y, bf.y),
                         pk2(bf.z, bf.z), pk2(bf.w, bf.w) };
#pragma unroll
            for (int i = 0; i < 4; i++)
#pragma unroll
                for (int j = 0; j < 4; j++)
                    fma2(acc[i][j], a[i], b[j]);
        }

        if (kt + 1 < ktiles) {
            const int nb = buf ^ 1;
            sA[nb][4 * lq + 0][lmA] = ra0.x; sA[nb][4 * lq + 1][lmA] = ra0.y;
            sA[nb][4 * lq + 2][lmA] = ra0.z; sA[nb][4 * lq + 3][lmA] = ra0.w;
            sA[nb][4 * lq + 0][lmA + 64] = ra1.x; sA[nb][4 * lq + 1][lmA + 64] = ra1.y;
            sA[nb][4 * lq + 2][lmA + 64] = ra1.z; sA[nb][4 * lq + 3][lmA + 64] = ra1.w;
            sB[nb][4 * lq + 0][lnB] = rb.x; sB[nb][4 * lq + 1][lnB] = rb.y;
            sB[nb][4 * lq + 2][lnB] = rb.z; sB[nb][4 * lq + 3][lnB] = rb.w;
        }
        __syncthreads();
    }

    // --- epilogue ---
    float bj[4];
#pragma unroll
    for (int j = 0; j < 4; j++) {
        int n = n0 + tn * 4 + j;
        bj[j] = (n < N) ? bias[n] : 0.f;
    }
    const bool vec = (n0 + BN <= N) && ((N & 3) == 0);

#pragma unroll
    for (int i = 0; i < 4; i++) {
        float lo[4], hi[4];
#pragma unroll
        for (int j = 0; j < 4; j++) {
            upk2(acc[i][j], lo[j], hi[j]);
            lo[j] += bj[j];
            hi[j] += bj[j];
        }
        size_t mlo = (size_t)(m0 + tm * 8 + 2 * i);
        float* C0 = C + mlo * N + n0 + tn * 4;
        float* C1 = C0 + N;
        if (vec) {
            *(float4*)C0 = make_float4(lo[0], lo[1], lo[2], lo[3]);
            *(float4*)C1 = make_float4(hi[0], hi[1], hi[2], hi[3]);
        } else {
#pragma unroll
            for (int j = 0; j < 4; j++) {
                int n = n0 + tn * 4 + j;
                if (n < N) { C0[j] = lo[j]; C1[j] = hi[j]; }
            }
        }
    }
}

// ============ LSTM recurrence over the BATCH axis ============
// T=512 independent lanes; 4 lanes per CTA (128 CTAs), 64 sequential steps.
// W_hh row in registers; h lane-interleaved float2; hs written with row
// stride KP3=64, pad cols zeroed.
__device__ __forceinline__ float sigm_f(float x) { return 1.f / (1.f + __expf(-x)); }
__device__ __forceinline__ float tanh_f(float x) { return 2.f / (1.f + __expf(-2.f * x)) - 1.f; }

__global__ void __launch_bounds__(256)
lstm_rec_kernel(const float* __restrict__ xg, const float* __restrict__ W_hh,
                const float* __restrict__ b_hh, float* __restrict__ hs)
{
    __shared__ __align__(8) float2 h01[H_], h23[H_];
    __shared__ __align__(8) float2 g01[G_], g23[G_];

    const int tid   = threadIdx.x;
    const int lane0 = blockIdx.x * 4;

    float w[H_];
    float bh = 0.f;
    if (tid < G_) {
#pragma unroll
        for (int k = 0; k < H_; k++) w[k] = W_hh[tid * H_ + k];
        bh = b_hh[tid];
    }
    if (tid < H_) { h01[tid] = make_float2(0.f, 0.f); h23[tid] = make_float2(0.f, 0.f); }
    float c = 0.f;
    __syncthreads();

    for (int b = 0; b < B_; b++) {
        if (tid < G_) {
            const float* xr = xg + (size_t)(b * T_ + lane0) * G_ + tid;
            u64 a01  = pk2(xr[0]      + bh, xr[G_]     + bh);
            u64 a23  = pk2(xr[2 * G_] + bh, xr[3 * G_] + bh);
            u64 a01b = 0ULL, a23b = 0ULL;
#pragma unroll
            for (int k = 0; k < H_; k += 2) {
                u64 hA0 = *(const u64*)&h01[k];
                u64 hA1 = *(const u64*)&h23[k];
                u64 hB0 = *(const u64*)&h01[k + 1];
                u64 hB1 = *(const u64*)&h23[k + 1];
                u64 wd0 = pk2(w[k],     w[k]);
                u64 wd1 = pk2(w[k + 1], w[k + 1]);
                fma2(a01,  hA0, wd0);
                fma2(a23,  hA1, wd0);
                fma2(a01b, hB0, wd1);
                fma2(a23b, hB1, wd1);
            }
            add2(a01, a01b);
            add2(a23, a23b);
            *(u64*)&g01[tid] = a01;
            *(u64*)&g23[tid] = a23;
        }
        __syncthreads();

        if (tid < 4 * H_) {               // 200 update threads
            int l  = tid / H_;
            int hh = tid - l * H_;
            const float* gb = (l < 2) ? (const float*)g01 : (const float*)g23;
            int off = l & 1;
            float ig = gb[2 * hh            + off];
            float fg = gb[2 * (H_ + hh)     + off];
            float gg = gb[2 * (2 * H_ + hh) + off];
            float og = gb[2 * (3 * H_ + hh) + off];
            float si = sigm_f(ig);
            float sf = sigm_f(fg);
            float so = sigm_f(og);
            c = sf * c + si * tanh_f(gg);
            float h2 = so * tanh_f(c);
            float* hb = (l < 2) ? (float*)h01 : (float*)h23;
            hb[2 * hh + off] = h2;
            hs[(size_t)(b * T_ + lane0 + l) * KP3 + hh] = h2;
        } else {                           // 56 threads zero the pad cols
            int r = tid - 4 * H_;          // 0..55
            int l = r / 14, j = r - l * 14;
            hs[(size_t)(b * T_ + lane0 + l) * KP3 + H_ + j] = 0.f;
        }
        __syncthreads();
    }
}

// ---------------- launch ----------------
extern "C" void kernel_launch(void* const* d_in, const int* in_sizes, int n_in,
                              void* d_out, int out_size)
{
    const float* x     = (const float*)d_in[0];
    const float* W_ih  = (const float*)d_in[1];
    const float* W_hh  = (const float*)d_in[2];
    const float* b_ih  = (const float*)d_in[3];
    const float* b_hh  = (const float*)d_in[4];
    const float* W_out = (const float*)d_in[5];
    const float* b_out = (const float*)d_in[6];
    float* out = (float*)d_out;

    float *xp, *wih, *wout, *xg, *hs;
    cudaGetSymbolAddress((void**)&xp,   g_xpad);
    cudaGetSymbolAddress((void**)&wih,  g_wih);
    cudaGetSymbolAddress((void**)&wout, g_wout);
    cudaGetSymbolAddress((void**)&xg,   g_xg);
    cudaGetSymbolAddress((void**)&hs,   g_hs);

    // 0) pad x and weights for aligned float4 loads
    {
        size_t n = (size_t)M_ * KP1;
        pad_x_kernel<<<(unsigned)((n + 255) / 256), 256>>>(x, xp);
        int nw = G_ * KP1;   // 105600 > F_*KP3 = 32832
        pad_w_kernel<<<(nw + 255) / 256, 256>>>(W_ih, W_out, wih, wout);
    }

    dim3 blk(256);

    // 1) xg = x @ W_ih^T + b_ih   (M=32768, N=200, KP=528)
    gemm_abt_bias<<<dim3(M_ / BM, (G_ + BN - 1) / BN), blk>>>(xp, wih, b_ih, xg, M_, G_, KP1);

    // 2) batch-axis LSTM recurrence -> hs (32768 x 64 padded)
    lstm_rec_kernel<<<T_ / 4, blk>>>(xg, W_hh, b_hh, hs);

    // 3) out = hs @ W_out^T + b_out   (M=32768, N=513, KP=64)
    gemm_abt_bias<<<dim3(M_ / BM, (F_ + BN - 1) / BN), blk>>>(hs, wout, b_out, out, M_, F_, KP3);
}

// round 6
// speedup vs baseline: 2.6395x; 1.1681x over previous
#include <cuda_runtime.h>
#include <math.h>

// Problem constants
#define B_   64
#define T_   512
#define H_   50
#define G_   200      // 4*H
#define F_   513
#define M_   (B_*T_)  // 32768
#define KP1  528      // F padded (B rows only)
#define KP3  64       // H padded

// Scratch (device globals)
__device__ float g_wih [(size_t)G_ * KP1];    // padded W_ih (200 x 528)
__device__ float g_wout[(size_t)F_ * KP3];    // padded W_out (513 x 64)
__device__ float g_xg  [(size_t)M_ * G_];     // 26.2 MB gates
__device__ float g_hs  [(size_t)M_ * KP3];    // 8.4 MB hidden (padded rows)

typedef unsigned long long u64;

// ---------------- f32x2 packed helpers ----------------
__device__ __forceinline__ u64 pk2(float lo, float hi) {
    u64 r;
    asm("mov.b64 %0, {%1, %2};" : "=l"(r) : "f"(lo), "f"(hi));
    return r;
}
__device__ __forceinline__ void upk2(u64 v, float& lo, float& hi) {
    asm("mov.b64 {%0, %1}, %2;" : "=f"(lo), "=f"(hi) : "l"(v));
}
__device__ __forceinline__ void fma2(u64& d, u64 a, u64 b) {
    asm("fma.rn.f32x2 %0, %1, %2, %0;" : "+l"(d) : "l"(a), "l"(b));
}
__device__ __forceinline__ void add2(u64& d, u64 a) {
    asm("add.rn.f32x2 %0, %0, %1;" : "+l"(d) : "l"(a));
}

// ---------------- weight padding prepass (tiny) ----------------
__global__ void pad_w_kernel(const float* __restrict__ wih, const float* __restrict__ wout,
                             float* __restrict__ wihp, float* __restrict__ woutp)
{
    int i = blockIdx.x * blockDim.x + threadIdx.x;
    if (i < G_ * KP1) {
        int g = i / KP1, k = i - g * KP1;
        wihp[i] = (k < F_) ? wih[g * F_ + k] : 0.f;
    }
    if (i < F_ * KP3) {
        int f = i / KP3, k = i - f * KP3;
        woutp[i] = (k < H_) ? wout[f * H_ + k] : 0.f;
    }
}

// ============ C = A(M x KA) * B(N x KP)^T + bias(N) ============
// B rows are KP-padded (zeros), 16B-aligned. A handled per VECA:
//   VECA=true : A rows KP-padded & 16B-aligned -> float4 loads, no predicates
//   VECA=false: A rows raw length KACT (any alignment) -> scalar coalesced
//               loads (warp = 2 rows x 16 consecutive k), k<KACT predicated
// BM=128, BN=64, BK=16, TM=8, TN=4, 256 threads. Double-buffered, 1 sync/tile.
#define BM 128
#define BN 64
#define BK 16
#define SA_ST (BM + 4)
#define SB_ST (BN + 4)

template<bool VECA>
__global__ void __launch_bounds__(256, 2)
gemm_abt_bias(const float* __restrict__ A, const float* __restrict__ Bm,
              const float* __restrict__ bias, float* __restrict__ C,
              int M, int N, int KP, int KACT)
{
    __shared__ __align__(16) float sA[2][BK][SA_ST];
    __shared__ __align__(16) float sB[2][BK][SB_ST];

    const int tid = threadIdx.x;
    const int tn  = tid & 15;
    const int tm  = tid >> 4;
    const int m0  = blockIdx.x * BM;
    const int n0  = blockIdx.y * BN;

    // B load map (float4): k-quad + row
    const int lq  = tid & 3;
    const int lnB = tid >> 2;          // 0..63
    // scalar A load map: k + row
    const int lk  = tid & 15;          // k within tile
    const int lr  = tid >> 4;          // 0..15 (rows lr + 16*r)

    u64 acc[4][4];
#pragma unroll
    for (int i = 0; i < 4; i++)
#pragma unroll
        for (int j = 0; j < 4; j++) acc[i][j] = 0ULL;

    const int ktiles = (KACT + BK - 1) / BK;

    float4 va0, va1, vb;
    float  sa[8];

    // ---- prologue: fetch tile 0 ----
    {
        if (VECA) {
            const float* Ap = A + (size_t)(m0 + lnB) * KP + 4 * lq;
            va0 = *(const float4*)Ap;
            va1 = *(const float4*)(Ap + (size_t)64 * KP);
        } else {
            bool kok = (lk < KACT);
#pragma unroll
            for (int r = 0; r < 8; r++) {
                int m = m0 + lr + 16 * r;
                sa[r] = kok ? A[(size_t)m * KACT + lk] : 0.f;
            }
        }
        int n = n0 + lnB;
        vb = (n < N) ? *(const float4*)(Bm + (size_t)n * KP + 4 * lq)
                     : make_float4(0.f, 0.f, 0.f, 0.f);
        // stage
        if (VECA) {
            sA[0][4 * lq + 0][lnB] = va0.x; sA[0][4 * lq + 1][lnB] = va0.y;
            sA[0][4 * lq + 2][lnB] = va0.z; sA[0][4 * lq + 3][lnB] = va0.w;
            sA[0][4 * lq + 0][lnB + 64] = va1.x; sA[0][4 * lq + 1][lnB + 64] = va1.y;
            sA[0][4 * lq + 2][lnB + 64] = va1.z; sA[0][4 * lq + 3][lnB + 64] = va1.w;
        } else {
#pragma unroll
            for (int r = 0; r < 8; r++) sA[0][lk][lr + 16 * r] = sa[r];
        }
        sB[0][4 * lq + 0][lnB] = vb.x; sB[0][4 * lq + 1][lnB] = vb.y;
        sB[0][4 * lq + 2][lnB] = vb.z; sB[0][4 * lq + 3][lnB] = vb.w;
    }
    __syncthreads();

    for (int kt = 0; kt < ktiles; kt++) {
        const int buf = kt & 1;

        if (kt + 1 < ktiles) {
            const int k0 = (kt + 1) * BK;
            if (VECA) {
                const float* Ap = A + (size_t)(m0 + lnB) * KP + k0 + 4 * lq;
                va0 = *(const float4*)Ap;
                va1 = *(const float4*)(Ap + (size_t)64 * KP);
            } else {
                bool kok = (k0 + lk < KACT);
#pragma unroll
                for (int r = 0; r < 8; r++) {
                    int m = m0 + lr + 16 * r;
                    sa[r] = kok ? A[(size_t)m * KACT + k0 + lk] : 0.f;
                }
            }
            int n = n0 + lnB;
            vb = (n < N) ? *(const float4*)(Bm + (size_t)n * KP + k0 + 4 * lq)
                         : make_float4(0.f, 0.f, 0.f, 0.f);
        }

#pragma unroll
        for (int kk = 0; kk < BK; kk++) {
            const ulonglong2* pa = (const ulonglong2*)&sA[buf][kk][tm * 8];
            ulonglong2 a01 = pa[0], a23 = pa[1];
            float4 bf = *(const float4*)&sB[buf][kk][tn * 4];
            u64 a[4] = { a01.x, a01.y, a23.x, a23.y };
            u64 b[4] = { pk2(bf.x, bf.x), pk2(bf.y, bf.y),
                         pk2(bf.z, bf.z), pk2(bf.w, bf.w) };
#pragma unroll
            for (int i = 0; i < 4; i++)
#pragma unroll
                for (int j = 0; j < 4; j++)
                    fma2(acc[i][j], a[i], b[j]);
        }

        if (kt + 1 < ktiles) {
            const int nb = buf ^ 1;
            if (VECA) {
                sA[nb][4 * lq + 0][lnB] = va0.x; sA[nb][4 * lq + 1][lnB] = va0.y;
                sA[nb][4 * lq + 2][lnB] = va0.z; sA[nb][4 * lq + 3][lnB] = va0.w;
                sA[nb][4 * lq + 0][lnB + 64] = va1.x; sA[nb][4 * lq + 1][lnB + 64] = va1.y;
                sA[nb][4 * lq + 2][lnB + 64] = va1.z; sA[nb][4 * lq + 3][lnB + 64] = va1.w;
            } else {
#pragma unroll
                for (int r = 0; r < 8; r++) sA[nb][lk][lr + 16 * r] = sa[r];
            }
            sB[nb][4 * lq + 0][lnB] = vb.x; sB[nb][4 * lq + 1][lnB] = vb.y;
            sB[nb][4 * lq + 2][lnB] = vb.z; sB[nb][4 * lq + 3][lnB] = vb.w;
        }
        __syncthreads();
    }

    // ---- epilogue ----
    float bj[4];
#pragma unroll
    for (int j = 0; j < 4; j++) {
        int n = n0 + tn * 4 + j;
        bj[j] = (n < N) ? bias[n] : 0.f;
    }
    const bool vec = (n0 + BN <= N) && ((N & 3) == 0);

#pragma unroll
    for (int i = 0; i < 4; i++) {
        float lo[4], hi[4];
#pragma unroll
        for (int j = 0; j < 4; j++) {
            upk2(acc[i][j], lo[j], hi[j]);
            lo[j] += bj[j];
            hi[j] += bj[j];
        }
        size_t mlo = (size_t)(m0 + tm * 8 + 2 * i);
        float* C0 = C + mlo * N + n0 + tn * 4;
        float* C1 = C0 + N;
        if (vec) {
            *(float4*)C0 = make_float4(lo[0], lo[1], lo[2], lo[3]);
            *(float4*)C1 = make_float4(hi[0], hi[1], hi[2], hi[3]);
        } else {
#pragma unroll
            for (int j = 0; j < 4; j++) {
                int n = n0 + tn * 4 + j;
                if (n < N) { C0[j] = lo[j]; C1[j] = hi[j]; }
            }
        }
    }
}

// ============ LSTM recurrence over the BATCH axis ============
// 128 CTAs x 4 lanes, 64 sequential steps. W_hh row in registers.
// h stored as float4[50] (4 lanes per k -> LDS.128). xg loads for step b+1
// issued at the top of step b (hides DRAM latency behind the matvec).
__device__ __forceinline__ float sigm_f(float x) { return 1.f / (1.f + __expf(-x)); }
__device__ __forceinline__ float tanh_f(float x) { return 2.f / (1.f + __expf(-2.f * x)) - 1.f; }

__global__ void __launch_bounds__(256)
lstm_rec_kernel(const float* __restrict__ xg, const float* __restrict__ W_hh,
                const float* __restrict__ b_hh, float* __restrict__ hs)
{
    __shared__ __align__(16) float4 h4[H_];
    __shared__ __align__(16) float4 g4[G_];

    const int tid   = threadIdx.x;
    const int lane0 = blockIdx.x * 4;

    float w[H_];
    float bh = 0.f;
    if (tid < G_) {
#pragma unroll
        for (int k = 0; k < H_; k++) w[k] = W_hh[tid * H_ + k];
        bh = b_hh[tid];
    }
    if (tid < H_) h4[tid] = make_float4(0.f, 0.f, 0.f, 0.f);
    float c = 0.f;
    __syncthreads();

    float xc0 = 0.f, xc1 = 0.f, xc2 = 0.f, xc3 = 0.f;
    if (tid < G_) {
        const float* xr = xg + (size_t)lane0 * G_ + tid;
        xc0 = xr[0]; xc1 = xr[G_]; xc2 = xr[2 * G_]; xc3 = xr[3 * G_];
    }

    for (int b = 0; b < B_; b++) {
        // prefetch next step's xg (independent -> LDG in flight during matvec)
        float xn0 = 0.f, xn1 = 0.f, xn2 = 0.f, xn3 = 0.f;
        if (tid < G_ && b + 1 < B_) {
            const float* xr = xg + (size_t)((b + 1) * T_ + lane0) * G_ + tid;
            xn0 = xr[0]; xn1 = xr[G_]; xn2 = xr[2 * G_]; xn3 = xr[3 * G_];
        }

        if (tid < G_) {
            u64 a01 = pk2(xc0 + bh, xc1 + bh);
            u64 a23 = pk2(xc2 + bh, xc3 + bh);
            u64 c01 = 0ULL, c23 = 0ULL;
#pragma unroll
            for (int k = 0; k < H_; k += 2) {
                ulonglong2 hv0 = *(const ulonglong2*)&h4[k];
                ulonglong2 hv1 = *(const ulonglong2*)&h4[k + 1];
                u64 wd0 = pk2(w[k],     w[k]);
                u64 wd1 = pk2(w[k + 1], w[k + 1]);
                fma2(a01, hv0.x, wd0);
                fma2(a23, hv0.y, wd0);
                fma2(c01, hv1.x, wd1);
                fma2(c23, hv1.y, wd1);
            }
            add2(a01, c01);
            add2(a23, c23);
            ulonglong2 st; st.x = a01; st.y = a23;
            *(ulonglong2*)&g4[tid] = st;
        }
        __syncthreads();

        if (tid < 4 * H_) {                 // 200 update threads: (lane l, unit hh)
            int l  = tid / H_;
            int hh = tid - l * H_;
            const float* gp = (const float*)g4;
            float ig = gp[4 * hh            + l];
            float fg = gp[4 * (H_ + hh)     + l];
            float gg = gp[4 * (2 * H_ + hh) + l];
            float og = gp[4 * (3 * H_ + hh) + l];
            float si = sigm_f(ig);
            float sf = sigm_f(fg);
            float so = sigm_f(og);
            c = sf * c + si * tanh_f(gg);
            float h2 = so * tanh_f(c);
            ((float*)h4)[4 * hh + l] = h2;
            hs[(size_t)(b * T_ + lane0 + l) * KP3 + hh] = h2;
        } else {                            // 56 threads zero the pad cols
            int r = tid - 4 * H_;
            int l = r / 14, j = r - l * 14;
            hs[(size_t)(b * T_ + lane0 + l) * KP3 + H_ + j] = 0.f;
        }
        __syncthreads();

        xc0 = xn0; xc1 = xn1; xc2 = xn2; xc3 = xn3;
    }
}

// ---------------- launch ----------------
extern "C" void kernel_launch(void* const* d_in, const int* in_sizes, int n_in,
                              void* d_out, int out_size)
{
    const float* x     = (const float*)d_in[0];
    const float* W_ih  = (const float*)d_in[1];
    const float* W_hh  = (const float*)d_in[2];
    const float* b_ih  = (const float*)d_in[3];
    const float* b_hh  = (const float*)d_in[4];
    const float* W_out = (const float*)d_in[5];
    const float* b_out = (const float*)d_in[6];
    float* out = (float*)d_out;

    float *wih, *wout, *xg, *hs;
    cudaGetSymbolAddress((void**)&wih,  g_wih);
    cudaGetSymbolAddress((void**)&wout, g_wout);
    cudaGetSymbolAddress((void**)&xg,   g_xg);
    cudaGetSymbolAddress((void**)&hs,   g_hs);

    // 0) pad weights only (tiny)
    {
        int nw = G_ * KP1;   // 105600 > F_*KP3 = 32832
        pad_w_kernel<<<(nw + 255) / 256, 256>>>(W_ih, W_out, wih, wout);
    }

    dim3 blk(256);

    // 1) xg = x @ W_ih^T + b_ih   (M=32768, N=200; A raw K=513, B padded 528)
    gemm_abt_bias<false>
        <<<dim3(M_ / BM, (G_ + BN - 1) / BN), blk>>>(x, wih, b_ih, xg, M_, G_, KP1, F_);

    // 2) batch-axis LSTM recurrence -> hs (32768 x 64 padded)
    lstm_rec_kernel<<<T_ / 4, blk>>>(xg, W_hh, b_hh, hs);

    // 3) out = hs @ W_out^T + b_out   (M=32768, N=513; A padded 64, B padded 64)
    gemm_abt_bias<true>
        <<<dim3(M_ / BM, (F_ + BN - 1) / BN), blk>>>(hs, wout, b_out, out, M_, F_, KP3, KP3);
}

// round 10
// speedup vs baseline: 4.0212x; 1.5235x over previous
#include <cuda_runtime.h>
#include <cuda_bf16.h>
#include <math.h>

// Problem constants
#define B_   64
#define T_   512
#define H_   50
#define G_   200      // 4*H
#define F_   513
#define M_   (B_*T_)  // 32768
#define KP3  64       // H padded for gemm3 A rows

// GEMM1: N padded to 224 (2 n-CTAs x 112), K=512 via 32 k16 steps + fp32 rank-1 fixup (col 512)
#define G1_KS 32
#define G1_NT 28            // 224/8 n-tiles total
// GEMM3: N padded to 560 (5 n-CTAs x 112), K=64 -> 4 k16 steps
#define G3_KS 4
#define G3_NT 70            // 560/8

// Scratch (device globals)
__device__ float  g_xg[(size_t)M_ * G_];
__device__ float  g_hs[(size_t)M_ * KP3];
__device__ uint4  g_b1[G1_KS * G1_NT * 32];   // W_ih frags: {b0h,b1h,b0l,b1l} per lane
__device__ uint4  g_b3[G3_KS * G3_NT * 32];   // W_out frags
__device__ float2 g_tail1[224];               // {W_ih[n][512], b_ih[n]}
__device__ float2 g_tail3[560];               // {0, b_out[n]}

typedef unsigned long long u64;

// ---------------- f32x2 helpers (recurrence) ----------------
__device__ __forceinline__ u64 pk2(float lo, float hi) {
    u64 r; asm("mov.b64 %0, {%1, %2};" : "=l"(r) : "f"(lo), "f"(hi)); return r;
}
__device__ __forceinline__ void fma2(u64& d, u64 a, u64 b) {
    asm("fma.rn.f32x2 %0, %1, %2, %0;" : "+l"(d) : "l"(a), "l"(b));
}
__device__ __forceinline__ void add2(u64& d, u64 a) {
    asm("add.rn.f32x2 %0, %0, %1;" : "+l"(d) : "l"(a));
}

// ---------------- bf16 split helpers ----------------
// pack (v0 -> low half, v1 -> high half) as bf16x2; lo = residual split
__device__ __forceinline__ void split2(float v0, float v1, unsigned& h, unsigned& l) {
    __nv_bfloat162 bh = __float22bfloat162_rn(make_float2(v0, v1));
    h = *(unsigned*)&bh;
    float f0 = __uint_as_float(h << 16);
    float f1 = __uint_as_float(h & 0xffff0000u);
    __nv_bfloat162 bl = __float22bfloat162_rn(make_float2(v0 - f0, v1 - f1));
    l = *(unsigned*)&bl;
}

// ---------------- warp MMA m16n8k16 bf16 (baseline PTX, sm_80+) ----------------
__device__ __forceinline__ void mma16816(float* d, const unsigned* a,
                                         unsigned b0, unsigned b1) {
    asm volatile(
        "mma.sync.aligned.m16n8k16.row.col.f32.bf16.bf16.f32 "
        "{%0,%1,%2,%3}, {%4,%5,%6,%7}, {%8,%9}, {%0,%1,%2,%3};"
        : "+f"(d[0]), "+f"(d[1]), "+f"(d[2]), "+f"(d[3])
        : "r"(a[0]), "r"(a[1]), "r"(a[2]), "r"(a[3]), "r"(b0), "r"(b1));
}

// ---------------- prepass: pack B fragments ----------------
// For mma .row.col, lane l of a k16n8 B-tile holds:
//   b0 = B[n = l/4][k0 + 2(l%4) + {0,1}],  b1 = same rows, k += 8
__global__ void pack_b1(const float* __restrict__ wih, uint4* __restrict__ bp,
                        const float* __restrict__ bih, float2* __restrict__ tail)
{
    int idx = blockIdx.x * 256 + threadIdx.x;
    if (idx < 224)
        tail[idx] = (idx < G_) ? make_float2(wih[idx * F_ + 512], bih[idx])
                               : make_float2(0.f, 0.f);
    if (idx >= G1_KS * G1_NT * 32) return;
    int kt   = idx / (G1_NT * 32);
    int rem  = idx - kt * (G1_NT * 32);
    int lane = rem & 31;
    int nt   = rem >> 5;
    int n    = nt * 8 + (lane >> 2);
    int k0   = kt * 16 + (lane & 3) * 2;     // <= 507, always < 512
    float v0 = 0.f, v1 = 0.f, v2 = 0.f, v3 = 0.f;
    if (n < G_) {
        const float* wr = wih + (size_t)n * F_;
        v0 = wr[k0]; v1 = wr[k0 + 1]; v2 = wr[k0 + 8]; v3 = wr[k0 + 9];
    }
    unsigned h0, l0, h1, l1;
    split2(v0, v1, h0, l0);
    split2(v2, v3, h1, l1);
    bp[idx] = make_uint4(h0, h1, l0, l1);
}

__global__ void pack_b3(const float* __restrict__ wout, uint4* __restrict__ bp,
                        const float* __restrict__ bout, float2* __restrict__ tail)
{
    int idx = blockIdx.x * 256 + threadIdx.x;
    if (idx < 560)
        tail[idx] = make_float2(0.f, (idx < F_) ? bout[idx] : 0.f);
    if (idx >= G3_KS * G3_NT * 32) return;
    int kt   = idx / (G3_NT * 32);
    int rem  = idx - kt * (G3_NT * 32);
    int lane = rem & 31;
    int nt   = rem >> 5;
    int n    = nt * 8 + (lane >> 2);
    int k0   = kt * 16 + (lane & 3) * 2;
    float v0 = 0.f, v1 = 0.f, v2 = 0.f, v3 = 0.f;
    if (n < F_) {
        const float* wr = wout + (size_t)n * H_;
        if (k0     < H_) v0 = wr[k0];
        if (k0 + 1 < H_) v1 = wr[k0 + 1];
        if (k0 + 8 < H_) v2 = wr[k0 + 8];
        if (k0 + 9 < H_) v3 = wr[k0 + 9];
    }
    unsigned h0, l0, h1, l1;
    split2(v0, v1, h0, l0);
    split2(v2, v3, h1, l1);
    bp[idx] = make_uint4(h0, h1, l0, l1);
}

// ============ C = A(M x astride) * B^T + tail fixup, via warp mma ============
// 256 threads = 8 warps as 4(M) x 2(N); warp tile m32 x n56 (2 m-tiles, 7 n-tiles).
// A fp32 loaded scalar (4B-aligned rows ok), split to bf16 hi/lo in registers.
// Split-bf16: acc += Ah*Bh + Ah*Bl + Al*Bh. No smem, no syncs.
// Epilogue: out = acc + xa * tail.x + tail.y  (fp32 rank-1 fixup + bias).
template<int KSTEPS, int NTTOT>
__global__ void __launch_bounds__(256)
gemm_mma(const float* __restrict__ A, int astride, int fixk,
         const uint4* __restrict__ bp, const float2* __restrict__ tail,
         float* __restrict__ C, int N)
{
    const int tid  = threadIdx.x, wid = tid >> 5, lane = tid & 31;
    const int wm   = wid & 3, wn = wid >> 2;
    const int m0   = blockIdx.y * 128 + wm * 32;
    const int nt0  = blockIdx.x * 14 + wn * 7;
    const int r    = lane >> 2;
    const int c2   = (lane & 3) * 2;

    float acc[2][7][4] = {};

    for (int kt = 0; kt < KSTEPS; kt++) {
        const int k0 = kt * 16;
        unsigned ah[2][4], al[2][4];
#pragma unroll
        for (int i = 0; i < 2; i++) {
            const float* p0 = A + (size_t)(m0 + i * 16 + r) * astride + k0 + c2;
            const float* p1 = p0 + 8 * astride;
            float v00 = p0[0], v01 = p0[1];
            float v10 = p1[0], v11 = p1[1];
            float v02 = p0[8], v03 = p0[9];
            float v12 = p1[8], v13 = p1[9];
            split2(v00, v01, ah[i][0], al[i][0]);
            split2(v10, v11, ah[i][1], al[i][1]);
            split2(v02, v03, ah[i][2], al[i][2]);
            split2(v12, v13, ah[i][3], al[i][3]);
        }
        const uint4* bb = bp + ((size_t)kt * NTTOT + nt0) * 32 + lane;
#pragma unroll
        for (int t = 0; t < 7; t++) {
            uint4 b = bb[t * 32];
#pragma unroll
            for (int i = 0; i < 2; i++) {
                mma16816(acc[i][t], ah[i], b.x, b.y);   // hi * hi
                mma16816(acc[i][t], ah[i], b.z, b.w);   // hi * lo
                mma16816(acc[i][t], al[i], b.x, b.y);   // lo * hi
            }
        }
    }

    // ---- epilogue: rank-1 fixup + bias, scalar stores (output rows may be 4B-aligned) ----
#pragma unroll
    for (int i = 0; i < 2; i++) {
        const int r0 = m0 + i * 16 + r, r1 = r0 + 8;
        const float xa = A[(size_t)r0 * astride + fixk];
        const float xb = A[(size_t)r1 * astride + fixk];
        float* C0 = C + (size_t)r0 * N;
        float* C1 = C + (size_t)r1 * N;
#pragma unroll
        for (int t = 0; t < 7; t++) {
            int col = (nt0 + t) * 8 + c2;
            if (col < N) {
                float2 tw = tail[col];
                C0[col] = acc[i][t][0] + xa * tw.x + tw.y;
                C1[col] = acc[i][t][2] + xb * tw.x + tw.y;
            }
            if (col + 1 < N) {
                float2 tw = tail[col + 1];
                C0[col + 1] = acc[i][t][1] + xa * tw.x + tw.y;
                C1[col + 1] = acc[i][t][3] + xb * tw.x + tw.y;
            }
        }
    }
}

// ================= LSTM recurrence over the BATCH axis =================
__device__ __forceinline__ float sigm_f(float x) { return 1.f / (1.f + __expf(-x)); }
__device__ __forceinline__ float tanh_f(float x) { return 2.f / (1.f + __expf(-2.f * x)) - 1.f; }

__global__ void __launch_bounds__(256)
lstm_rec_kernel(const float* __restrict__ xg, const float* __restrict__ W_hh,
                const float* __restrict__ b_hh, float* __restrict__ hs)
{
    __shared__ __align__(16) float4 h4[H_];
    __shared__ __align__(16) float4 g4[G_];

    const int tid   = threadIdx.x;
    const int lane0 = blockIdx.x * 4;

    float w[H_];
    float bh = 0.f;
    if (tid < G_) {
#pragma unroll
        for (int k = 0; k < H_; k++) w[k] = W_hh[tid * H_ + k];
        bh = b_hh[tid];
    }
    if (tid < H_) h4[tid] = make_float4(0.f, 0.f, 0.f, 0.f);
    float c = 0.f;
    __syncthreads();

    float xc0 = 0.f, xc1 = 0.f, xc2 = 0.f, xc3 = 0.f;
    if (tid < G_) {
        const float* xr = xg + (size_t)lane0 * G_ + tid;
        xc0 = xr[0]; xc1 = xr[G_]; xc2 = xr[2 * G_]; xc3 = xr[3 * G_];
    }

    for (int b = 0; b < B_; b++) {
        float xn0 = 0.f, xn1 = 0.f, xn2 = 0.f, xn3 = 0.f;
        if (tid < G_ && b + 1 < B_) {
            const float* xr = xg + (size_t)((b + 1) * T_ + lane0) * G_ + tid;
            xn0 = xr[0]; xn1 = xr[G_]; xn2 = xr[2 * G_]; xn3 = xr[3 * G_];
        }

        if (tid < G_) {
            u64 a01 = pk2(xc0 + bh, xc1 + bh);
            u64 a23 = pk2(xc2 + bh, xc3 + bh);
            u64 c01 = 0ULL, c23 = 0ULL;
#pragma unroll
            for (int k = 0; k < H_; k += 2) {
                ulonglong2 hv0 = *(const ulonglong2*)&h4[k];
                ulonglong2 hv1 = *(const ulonglong2*)&h4[k + 1];
                u64 wd0 = pk2(w[k],     w[k]);
                u64 wd1 = pk2(w[k + 1], w[k + 1]);
                fma2(a01, hv0.x, wd0);
                fma2(a23, hv0.y, wd0);
                fma2(c01, hv1.x, wd1);
                fma2(c23, hv1.y, wd1);
            }
            add2(a01, c01);
            add2(a23, c23);
            ulonglong2 st; st.x = a01; st.y = a23;
            *(ulonglong2*)&g4[tid] = st;
        }
        __syncthreads();

        if (tid < 4 * H_) {
            int l  = tid / H_;
            int hh = tid - l * H_;
            const float* gp = (const float*)g4;
            float ig = gp[4 * hh            + l];
            float fg = gp[4 * (H_ + hh)     + l];
            float gg = gp[4 * (2 * H_ + hh) + l];
            float og = gp[4 * (3 * H_ + hh) + l];
            float si = sigm_f(ig);
            float sf = sigm_f(fg);
            float so = sigm_f(og);
            c = sf * c + si * tanh_f(gg);
            float h2 = so * tanh_f(c);
            ((float*)h4)[4 * hh + l] = h2;
            hs[(size_t)(b * T_ + lane0 + l) * KP3 + hh] = h2;
        } else {
            int r = tid - 4 * H_;
            int l = r / 14, j = r - l * 14;
            hs[(size_t)(b * T_ + lane0 + l) * KP3 + H_ + j] = 0.f;
        }
        __syncthreads();

        xc0 = xn0; xc1 = xn1; xc2 = xn2; xc3 = xn3;
    }
}

// ---------------- launch ----------------
extern "C" void kernel_launch(void* const* d_in, const int* in_sizes, int n_in,
                              void* d_out, int out_size)
{
    const float* x     = (const float*)d_in[0];
    const float* W_ih  = (const float*)d_in[1];
    const float* W_hh  = (const float*)d_in[2];
    const float* b_ih  = (const float*)d_in[3];
    const float* b_hh  = (const float*)d_in[4];
    const float* W_out = (const float*)d_in[5];
    const float* b_out = (const float*)d_in[6];
    float* out = (float*)d_out;

    float *xg, *hs;
    uint4 *b1, *b3;
    float2 *t1, *t3;
    cudaGetSymbolAddress((void**)&xg, g_xg);
    cudaGetSymbolAddress((void**)&hs, g_hs);
    cudaGetSymbolAddress((void**)&b1, g_b1);
    cudaGetSymbolAddress((void**)&b3, g_b3);
    cudaGetSymbolAddress((void**)&t1, g_tail1);
    cudaGetSymbolAddress((void**)&t3, g_tail3);

    // 0) pack weight fragments (tiny)
    pack_b1<<<(G1_KS * G1_NT * 32 + 255) / 256, 256>>>(W_ih, b1, b_ih, t1);
    pack_b3<<<(G3_KS * G3_NT * 32 + 255) / 256, 256>>>(W_out, b3, b_out, t3);

    // 1) xg = x @ W_ih^T + b_ih   (split-bf16 warp mma, K=512 + rank-1 col 512)
    gemm_mma<G1_KS, G1_NT><<<dim3(2, 256), 256>>>(x, F_, 512, b1, t1, xg, G_);

    // 2) batch-axis LSTM recurrence -> hs (32768 x 64 padded)
    lstm_rec_kernel<<<T_ / 4, 256>>>(xg, W_hh, b_hh, hs);

    // 3) out = hs @ W_out^T + b_out (split-bf16 warp mma, K=64)
    gemm_mma<G3_KS, G3_NT><<<dim3(5, 256), 256>>>(hs, KP3, 0, b3, t3, out, F_);
}

// round 11
// speedup vs baseline: 4.0523x; 1.0077x over previous
#include <cuda_runtime.h>
#include <cuda_bf16.h>
#include <math.h>

// Problem constants
#define B_   64
#define T_   512
#define H_   50
#define G_   200      // 4*H
#define F_   513
#define M_   (B_*T_)  // 32768
#define KP3  64       // H padded for gemm3 A rows

// GEMM1: N padded to 224 (2 n-CTAs x 112), K=512 via 32 k16 steps + fp32 rank-1 fixup (col 512)
#define G1_KS 32
#define G1_NT 28            // 224/8 n-tiles total
// GEMM3: N padded to 560 (5 n-CTAs x 112), K=64 -> 4 k16 steps
#define G3_KS 4
#define G3_NT 70            // 560/8

// Scratch (device globals)
__device__ float  g_xg[(size_t)M_ * G_];
__device__ float  g_hs[(size_t)M_ * KP3];
__device__ uint4  g_b1[G1_KS * G1_NT * 32];   // W_ih frags: {b0h,b1h,b0l,b1l} per lane
__device__ uint4  g_b3[G3_KS * G3_NT * 32];   // W_out frags
__device__ float2 g_tail1[224];               // {W_ih[n][512], b_ih[n]}
__device__ float2 g_tail3[560];               // {0, b_out[n]}

typedef unsigned long long u64;

// ---------------- f32x2 helpers ----------------
__device__ __forceinline__ u64 pk2(float lo, float hi) {
    u64 r; asm("mov.b64 %0, {%1, %2};" : "=l"(r) : "f"(lo), "f"(hi)); return r;
}
__device__ __forceinline__ void upk2(u64 v, float& lo, float& hi) {
    asm("mov.b64 {%0, %1}, %2;" : "=f"(lo), "=f"(hi) : "l"(v));
}
__device__ __forceinline__ void fma2(u64& d, u64 a, u64 b) {
    asm("fma.rn.f32x2 %0, %1, %2, %0;" : "+l"(d) : "l"(a), "l"(b));
}

// ---------------- bf16 split helpers ----------------
__device__ __forceinline__ void split2(float v0, float v1, unsigned& h, unsigned& l) {
    __nv_bfloat162 bh = __float22bfloat162_rn(make_float2(v0, v1));
    h = *(unsigned*)&bh;
    float f0 = __uint_as_float(h << 16);
    float f1 = __uint_as_float(h & 0xffff0000u);
    __nv_bfloat162 bl = __float22bfloat162_rn(make_float2(v0 - f0, v1 - f1));
    l = *(unsigned*)&bl;
}

// ---------------- warp MMA m16n8k16 bf16 ----------------
__device__ __forceinline__ void mma16816(float* d, const unsigned* a,
                                         unsigned b0, unsigned b1) {
    asm volatile(
        "mma.sync.aligned.m16n8k16.row.col.f32.bf16.bf16.f32 "
        "{%0,%1,%2,%3}, {%4,%5,%6,%7}, {%8,%9}, {%0,%1,%2,%3};"
        : "+f"(d[0]), "+f"(d[1]), "+f"(d[2]), "+f"(d[3])
        : "r"(a[0]), "r"(a[1]), "r"(a[2]), "r"(a[3]), "r"(b0), "r"(b1));
}

// ---------------- prepass: pack B fragments ----------------
__global__ void pack_b1(const float* __restrict__ wih, uint4* __restrict__ bp,
                        const float* __restrict__ bih, float2* __restrict__ tail)
{
    int idx = blockIdx.x * 256 + threadIdx.x;
    if (idx < 224)
        tail[idx] = (idx < G_) ? make_float2(wih[idx * F_ + 512], bih[idx])
                               : make_float2(0.f, 0.f);
    if (idx >= G1_KS * G1_NT * 32) return;
    int kt   = idx / (G1_NT * 32);
    int rem  = idx - kt * (G1_NT * 32);
    int lane = rem & 31;
    int nt   = rem >> 5;
    int n    = nt * 8 + (lane >> 2);
    int k0   = kt * 16 + (lane & 3) * 2;
    float v0 = 0.f, v1 = 0.f, v2 = 0.f, v3 = 0.f;
    if (n < G_) {
        const float* wr = wih + (size_t)n * F_;
        v0 = wr[k0]; v1 = wr[k0 + 1]; v2 = wr[k0 + 8]; v3 = wr[k0 + 9];
    }
    unsigned h0, l0, h1, l1;
    split2(v0, v1, h0, l0);
    split2(v2, v3, h1, l1);
    bp[idx] = make_uint4(h0, h1, l0, l1);
}

__global__ void pack_b3(const float* __restrict__ wout, uint4* __restrict__ bp,
                        const float* __restrict__ bout, float2* __restrict__ tail)
{
    int idx = blockIdx.x * 256 + threadIdx.x;
    if (idx < 560)
        tail[idx] = make_float2(0.f, (idx < F_) ? bout[idx] : 0.f);
    if (idx >= G3_KS * G3_NT * 32) return;
    int kt   = idx / (G3_NT * 32);
    int rem  = idx - kt * (G3_NT * 32);
    int lane = rem & 31;
    int nt   = rem >> 5;
    int n    = nt * 8 + (lane >> 2);
    int k0   = kt * 16 + (lane & 3) * 2;
    float v0 = 0.f, v1 = 0.f, v2 = 0.f, v3 = 0.f;
    if (n < F_) {
        const float* wr = wout + (size_t)n * H_;
        if (k0     < H_) v0 = wr[k0];
        if (k0 + 1 < H_) v1 = wr[k0 + 1];
        if (k0 + 8 < H_) v2 = wr[k0 + 8];
        if (k0 + 9 < H_) v3 = wr[k0 + 9];
    }
    unsigned h0, l0, h1, l1;
    split2(v0, v1, h0, l0);
    split2(v2, v3, h1, l1);
    bp[idx] = make_uint4(h0, h1, l0, l1);
}

// ============ C = A(M x astride) * B^T + tail fixup, via warp mma ============
template<int KSTEPS, int NTTOT>
__global__ void __launch_bounds__(256)
gemm_mma(const float* __restrict__ A, int astride, int fixk,
         const uint4* __restrict__ bp, const float2* __restrict__ tail,
         float* __restrict__ C, int N)
{
    const int tid  = threadIdx.x, wid = tid >> 5, lane = tid & 31;
    const int wm   = wid & 3, wn = wid >> 2;
    const int m0   = blockIdx.y * 128 + wm * 32;
    const int nt0  = blockIdx.x * 14 + wn * 7;
    const int r    = lane >> 2;
    const int c2   = (lane & 3) * 2;

    float acc[2][7][4] = {};

    for (int kt = 0; kt < KSTEPS; kt++) {
        const int k0 = kt * 16;
        unsigned ah[2][4], al[2][4];
#pragma unroll
        for (int i = 0; i < 2; i++) {
            const float* p0 = A + (size_t)(m0 + i * 16 + r) * astride + k0 + c2;
            const float* p1 = p0 + 8 * astride;
            float v00 = p0[0], v01 = p0[1];
            float v10 = p1[0], v11 = p1[1];
            float v02 = p0[8], v03 = p0[9];
            float v12 = p1[8], v13 = p1[9];
            split2(v00, v01, ah[i][0], al[i][0]);
            split2(v10, v11, ah[i][1], al[i][1]);
            split2(v02, v03, ah[i][2], al[i][2]);
            split2(v12, v13, ah[i][3], al[i][3]);
        }
        const uint4* bb = bp + ((size_t)kt * NTTOT + nt0) * 32 + lane;
#pragma unroll
        for (int t = 0; t < 7; t++) {
            uint4 b = bb[t * 32];
#pragma unroll
            for (int i = 0; i < 2; i++) {
                mma16816(acc[i][t], ah[i], b.x, b.y);   // hi * hi
                mma16816(acc[i][t], ah[i], b.z, b.w);   // hi * lo
                mma16816(acc[i][t], al[i], b.x, b.y);   // lo * hi
            }
        }
    }

#pragma unroll
    for (int i = 0; i < 2; i++) {
        const int r0 = m0 + i * 16 + r, r1 = r0 + 8;
        const float xa = A[(size_t)r0 * astride + fixk];
        const float xb = A[(size_t)r1 * astride + fixk];
        float* C0 = C + (size_t)r0 * N;
        float* C1 = C + (size_t)r1 * N;
#pragma unroll
        for (int t = 0; t < 7; t++) {
            int col = (nt0 + t) * 8 + c2;
            if (col < N) {
                float2 tw = tail[col];
                C0[col] = acc[i][t][0] + xa * tw.x + tw.y;
                C1[col] = acc[i][t][2] + xb * tw.x + tw.y;
            }
            if (col + 1 < N) {
                float2 tw = tail[col + 1];
                C0[col + 1] = acc[i][t][1] + xa * tw.x + tw.y;
                C1[col + 1] = acc[i][t][3] + xb * tw.x + tw.y;
            }
        }
    }
}

// ================= LSTM recurrence over the BATCH axis =================
// 128 CTAs x 448 threads = 2 independent groups of 224 threads (7 warps),
// each group owns 2 lanes for all 64 steps with its OWN named barrier.
// Groups interleave at issue: one group's barrier/MUFU hides under the
// other's matvec. Matvec inner loop: acc packed over k-pairs, W_hh packed
// as 25 u64 pairs in regs -> per k-pair: 2 LDS.64 (broadcast) + 2 FMA2.
__device__ __forceinline__ float sigm_f(float x) { return 1.f / (1.f + __expf(-x)); }
__device__ __forceinline__ float tanh_f(float x) { return 2.f / (1.f + __expf(-2.f * x)) - 1.f; }

__global__ void __launch_bounds__(448)
lstm_rec_kernel(const float* __restrict__ xg, const float* __restrict__ W_hh,
                const float* __restrict__ b_hh, float* __restrict__ hs)
{
    __shared__ __align__(8) float  hsh[2][2][64];    // [group][lane][k]
    __shared__ __align__(8) float2 gsh[2][G_];       // [group][gate] = {lane0, lane1}

    const int tid   = threadIdx.x;
    const int grp   = tid / 224;                     // warps 0-6 | 7-13
    const int lt    = tid - grp * 224;
    const int lane0 = blockIdx.x * 4 + grp * 2;
    const int barid = grp + 1;

    u64 wp[25];
    float bh = 0.f;
    if (lt < G_) {
        const float* wr = W_hh + lt * H_;
#pragma unroll
        for (int kk = 0; kk < 25; kk++) wp[kk] = pk2(wr[2 * kk], wr[2 * kk + 1]);
        bh = b_hh[lt];
    }
    if (lt < 64) { hsh[grp][0][lt] = 0.f; hsh[grp][1][lt] = 0.f; }
    float c = 0.f;
    __syncthreads();

    float xc0 = 0.f, xc1 = 0.f;
    if (lt < G_) {
        const float* xr = xg + (size_t)lane0 * G_ + lt;
        xc0 = xr[0]; xc1 = xr[G_];
    }

    for (int b = 0; b < B_; b++) {
        // prefetch next step's xg (LDG in flight during matvec)
        float xn0 = 0.f, xn1 = 0.f;
        if (lt < G_ && b + 1 < B_) {
            const float* xr = xg + (size_t)((b + 1) * T_ + lane0) * G_ + lt;
            xn0 = xr[0]; xn1 = xr[G_];
        }

        if (lt < G_) {
            // acc packed over k-pairs: {sum_even_k, sum_odd_k} per lane
            u64 a0 = pk2(xc0 + bh, 0.f);
            u64 a1 = pk2(xc1 + bh, 0.f);
#pragma unroll
            for (int kk = 0; kk < 25; kk++) {
                u64 h0 = *(const u64*)&hsh[grp][0][2 * kk];
                u64 h1 = *(const u64*)&hsh[grp][1][2 * kk];
                fma2(a0, h0, wp[kk]);
                fma2(a1, h1, wp[kk]);
            }
            float e0, e1, f0, f1;
            upk2(a0, e0, e1);
            upk2(a1, f0, f1);
            gsh[grp][lt] = make_float2(e0 + e1, f0 + f1);
        }
        asm volatile("bar.sync %0, 224;" :: "r"(barid) : "memory");

        if (lt < 2 * H_) {                    // 100 update threads: (lane l, unit hh)
            int l  = lt & 1;
            int hh = lt >> 1;
            const float* gp = (const float*)gsh[grp];
            float ig = gp[2 * hh            + l];
            float fg = gp[2 * (H_ + hh)     + l];
            float gg = gp[2 * (2 * H_ + hh) + l];
            float og = gp[2 * (3 * H_ + hh) + l];
            float si = sigm_f(ig);
            float sf = sigm_f(fg);
            float so = sigm_f(og);
            c = sf * c + si * tanh_f(gg);
            float h2 = so * tanh_f(c);
            hsh[grp][l][hh] = h2;
            hs[(size_t)(b * T_ + lane0 + l) * KP3 + hh] = h2;
        } else if (lt < 2 * H_ + 28) {        // 28 threads zero the pad cols
            int r = lt - 2 * H_;
            int l = r & 1, j = r >> 1;        // j 0..13
            hs[(size_t)(b * T_ + lane0 + l) * KP3 + H_ + j] = 0.f;
        }
        asm volatile("bar.sync %0, 224;" :: "r"(barid) : "memory");

        xc0 = xn0; xc1 = xn1;
    }
}

// ---------------- launch ----------------
extern "C" void kernel_launch(void* const* d_in, const int* in_sizes, int n_in,
                              void* d_out, int out_size)
{
    const float* x     = (const float*)d_in[0];
    const float* W_ih  = (const float*)d_in[1];
    const float* W_hh  = (const float*)d_in[2];
    const float* b_ih  = (const float*)d_in[3];
    const float* b_hh  = (const float*)d_in[4];
    const float* W_out = (const float*)d_in[5];
    const float* b_out = (const float*)d_in[6];
    float* out = (float*)d_out;

    float *xg, *hs;
    uint4 *b1, *b3;
    float2 *t1, *t3;
    cudaGetSymbolAddress((void**)&xg, g_xg);
    cudaGetSymbolAddress((void**)&hs, g_hs);
    cudaGetSymbolAddress((void**)&b1, g_b1);
    cudaGetSymbolAddress((void**)&b3, g_b3);
    cudaGetSymbolAddress((void**)&t1, g_tail1);
    cudaGetSymbolAddress((void**)&t3, g_tail3);

    // 0) pack weight fragments (tiny)
    pack_b1<<<(G1_KS * G1_NT * 32 + 255) / 256, 256>>>(W_ih, b1, b_ih, t1);
    pack_b3<<<(G3_KS * G3_NT * 32 + 255) / 256, 256>>>(W_out, b3, b_out, t3);

    // 1) xg = x @ W_ih^T + b_ih   (split-bf16 warp mma, K=512 + rank-1 col 512)
    gemm_mma<G1_KS, G1_NT><<<dim3(2, 256), 256>>>(x, F_, 512, b1, t1, xg, G_);

    // 2) batch-axis LSTM recurrence -> hs (32768 x 64 padded)
    lstm_rec_kernel<<<T_ / 4, 448>>>(xg, W_hh, b_hh, hs);

    // 3) out = hs @ W_out^T + b_out (split-bf16 warp mma, K=64)
    gemm_mma<G3_KS, G3_NT><<<dim3(5, 256), 256>>>(hs, KP3, 0, b3, t3, out, F_);
}